// round 8
// baseline (speedup 1.0000x reference)
#include <cuda_runtime.h>
#include <cstdint>

#define N_NODES 100000
#define N_EDGES 1600000
#define SCAN_BLK 512
#define NSCAN_BLKS 196   // 196*512 >= N_NODES

// ---------------- scratch (device globals; no allocation allowed) ----------
__device__ float g_y[N_NODES * 32];     // x @ W1_l
__device__ float g_z[N_NODES * 32];     // x @ W1_r
__device__ float g_h1[N_NODES * 32];
__device__ int2  g_edge[N_EDGES];       // packed (src, dst)
__device__ int   g_csr[N_EDGES];        // src ids grouped by dst
__device__ int   g_off[N_NODES + 1];    // counts -> exclusive offsets
__device__ int   g_part[N_NODES];       // scan partials
__device__ int   g_cur[N_NODES];        // bucket cursors
__device__ int   g_bsum[256];
__device__ int   g_is64;

// ---------------- JAX threefry2x32 (partitionable scheme) ------------------
struct TF2 { uint32_t a, b; };

__host__ __device__ constexpr uint32_t rotl32(uint32_t v, int r) {
    return (v << r) | (v >> (32 - r));
}

__host__ __device__ constexpr TF2 threefry(uint32_t k0, uint32_t k1,
                                           uint32_t x0, uint32_t x1) {
    const uint32_t ks0 = k0, ks1 = k1, ks2 = k0 ^ k1 ^ 0x1BD11BDAu;
    const int ra[4] = {13, 15, 26, 6};
    const int rb[4] = {17, 29, 16, 24};
    x0 += ks0; x1 += ks1;
#pragma unroll
    for (int i = 0; i < 4; i++) { x0 += x1; x1 = rotl32(x1, ra[i]); x1 ^= x0; }
    x0 += ks1; x1 += ks2 + 1u;
#pragma unroll
    for (int i = 0; i < 4; i++) { x0 += x1; x1 = rotl32(x1, rb[i]); x1 ^= x0; }
    x0 += ks2; x1 += ks0 + 2u;
#pragma unroll
    for (int i = 0; i < 4; i++) { x0 += x1; x1 = rotl32(x1, ra[i]); x1 ^= x0; }
    x0 += ks0; x1 += ks1 + 3u;
#pragma unroll
    for (int i = 0; i < 4; i++) { x0 += x1; x1 = rotl32(x1, rb[i]); x1 ^= x0; }
    x0 += ks1; x1 += ks2 + 4u;
#pragma unroll
    for (int i = 0; i < 4; i++) { x0 += x1; x1 = rotl32(x1, ra[i]); x1 ^= x0; }
    x0 += ks2; x1 += ks0 + 5u;
    return {x0, x1};
}

constexpr TF2 DK0 = threefry(0u, 42u, 0u, 0u);
constexpr TF2 DK1 = threefry(0u, 42u, 0u, 1u);

template <uint32_t K0, uint32_t K1>
__device__ __forceinline__ bool drop_bit(uint32_t j) {
    TF2 r = threefry(K0, K1, 0u, j);
    return ((r.a ^ r.b) >> 31) != 0;   // MSB set -> u >= 0.5 -> dropped
}

// ---------------- packed f32x2 helpers (sm_103a) ---------------------------
__device__ __forceinline__ unsigned long long pk2(float x, float y) {
    unsigned long long r;
    asm("mov.b64 %0, {%1, %2};" : "=l"(r) : "f"(x), "f"(y));
    return r;
}
__device__ __forceinline__ unsigned long long fma2(unsigned long long a,
                                                   unsigned long long b,
                                                   unsigned long long c) {
    unsigned long long d;
    asm("fma.rn.f32x2 %0, %1, %2, %3;" : "=l"(d) : "l"(a), "l"(b), "l"(c));
    return d;
}
__device__ __forceinline__ void upk2(unsigned long long v, float& x, float& y) {
    asm("mov.b64 {%0, %1}, %2;" : "=f"(x), "=f"(y) : "l"(v));
}

// ---------------- CSR-build chain (side stream) -----------------------------
__global__ void k_zero(const uint32_t* __restrict__ ei) {
    int i = blockIdx.x * 256 + threadIdx.x;
    if (i <= N_NODES) g_off[i] = 0;
    if (i == 0) {
        int is64 = 1;
        for (int k = 0; k < 64; k++)
            if (ei[2 * k + 1] != 0u) { is64 = 0; break; }
        g_is64 = is64;
    }
}

// pack edges + dst histogram
__global__ void k_prep(const uint32_t* __restrict__ ei) {
    int e = blockIdx.x * blockDim.x + threadIdx.x;
    if (e >= N_EDGES) return;
    int s, d;
    if (g_is64) {
        uint2 sv = reinterpret_cast<const uint2*>(ei)[e];
        uint2 dv = reinterpret_cast<const uint2*>(ei)[N_EDGES + e];
        s = (int)sv.x; d = (int)dv.x;
    } else {
        s = (int)ei[e];
        d = (int)ei[N_EDGES + e];
    }
    g_edge[e] = make_int2(s, d);
    atomicAdd(&g_off[d], 1);
}

// per-chunk exclusive scan; publish chunk totals
__global__ void k_scan_a() {
    __shared__ int sh[SCAN_BLK];
    int i = blockIdx.x * SCAN_BLK + threadIdx.x;
    int v = (i < N_NODES) ? g_off[i] : 0;
    sh[threadIdx.x] = v;
    __syncthreads();
    for (int o = 1; o < SCAN_BLK; o <<= 1) {
        int t = (threadIdx.x >= o) ? sh[threadIdx.x - o] : 0;
        __syncthreads();
        sh[threadIdx.x] += t;
        __syncthreads();
    }
    if (i < N_NODES) g_part[i] = sh[threadIdx.x] - v;    // exclusive in-block
    if (threadIdx.x == SCAN_BLK - 1) g_bsum[blockIdx.x] = sh[threadIdx.x];
}

// apply: each block redundantly reduces preceding chunk totals (cheap),
// then writes final offsets + cursors. replaces scan_b + scan_c.
__global__ void k_apply() {
    __shared__ int sh[SCAN_BLK];
    int tid = threadIdx.x, bid = blockIdx.x;
    int v = (tid < NSCAN_BLKS && tid < bid) ? g_bsum[tid] : 0;
    sh[tid] = v;
    __syncthreads();
    for (int o = SCAN_BLK / 2; o > 0; o >>= 1) {
        if (tid < o) sh[tid] += sh[tid + o];
        __syncthreads();
    }
    int base = sh[0];
    int i = bid * SCAN_BLK + tid;
    if (i < N_NODES) {
        int o = g_part[i] + base;
        g_off[i] = o;
        g_cur[i] = o;
    }
    if (bid == 0 && tid == 0) g_off[N_NODES] = N_EDGES;
}

__global__ void k_bucket() {
    int e = blockIdx.x * blockDim.x + threadIdx.x;
    if (e >= N_EDGES) return;
    int2 p = g_edge[e];
    int pos = atomicAdd(&g_cur[p.y], 1);
    g_csr[pos] = p.x;
}

// ---------------- main-stream kernels ---------------------------------------
// y = x @ W1_l, z = x @ W1_r; 4 nodes/warp, packed weights, packed FMA.
__global__ void __launch_bounds__(256) k_pre(const float* __restrict__ x,
                      const float* __restrict__ Wl,
                      const float* __restrict__ Wr) {
    __shared__ float2 swlr[64 * 32];      // (Wl, Wr) pairs, 16KB
    __shared__ float  rows[8][4][64];     // 8KB
    int tid = threadIdx.x;
    for (int i = tid; i < 2048; i += 256) swlr[i] = make_float2(Wl[i], Wr[i]);
    int w = tid >> 5, lane = tid & 31;
    int nb = blockIdx.x * 32 + w * 4;     // grid = 3125 exact
#pragma unroll
    for (int n = 0; n < 4; n++) {
        rows[w][n][lane]      = x[(nb + n) * 64 + lane];
        rows[w][n][32 + lane] = x[(nb + n) * 64 + 32 + lane];
    }
    __syncthreads();
    unsigned long long acc[4];
#pragma unroll
    for (int n = 0; n < 4; n++) acc[n] = pk2(0.f, 0.f);
#pragma unroll
    for (int k = 0; k < 64; k++) {
        float2 wv = swlr[k * 32 + lane];
        unsigned long long wp = pk2(wv.x, wv.y);
#pragma unroll
        for (int n = 0; n < 4; n++) {
            float xv = rows[w][n][k];
            acc[n] = fma2(pk2(xv, xv), wp, acc[n]);
        }
    }
#pragma unroll
    for (int n = 0; n < 4; n++) {
        float yl, yr;
        upk2(acc[n], yl, yr);
        g_y[(nb + n) * 32 + lane] = yl;
        g_z[(nb + n) * 32 + lane] = yr;
    }
}

// coalesced-index gather-sum of 32-wide rows for one node (warp-collective)
template <const float* BUF>
__device__ __forceinline__ float gather_row(int beg, int end, int lane) {
    float acc = 0.f;
    for (int j = beg; j < end; j += 32) {
        int n = end - j; if (n > 32) n = 32;
        int idx = (j + lane < end) ? __ldg(g_csr + j + lane) : 0;
        int t = 0;
        for (; t + 4 <= n; t += 4) {
            int s0 = __shfl_sync(0xffffffffu, idx, t);
            int s1 = __shfl_sync(0xffffffffu, idx, t + 1);
            int s2 = __shfl_sync(0xffffffffu, idx, t + 2);
            int s3 = __shfl_sync(0xffffffffu, idx, t + 3);
            float v0 = __ldg(BUF + s0 * 32 + lane);
            float v1 = __ldg(BUF + s1 * 32 + lane);
            float v2 = __ldg(BUF + s2 * 32 + lane);
            float v3 = __ldg(BUF + s3 * 32 + lane);
            acc += (v0 + v1) + (v2 + v3);
        }
        for (; t < n; t++) {
            int s = __shfl_sync(0xffffffffu, idx, t);
            acc += __ldg(BUF + s * 32 + lane);
        }
    }
    return acc;
}

// layer 1: warp per node; gather-sum y rows, fuse bias+z+lrelu+dropout
__global__ void k_agg1(const float* __restrict__ b) {
    int w = threadIdx.x >> 5, lane = threadIdx.x & 31;
    int node = blockIdx.x * 8 + w;                    // grid = 12500 exact
    int beg = g_off[node], end = g_off[node + 1];
    float acc = gather_row<g_y>(beg, end, lane);
    float inv = 1.0f / fmaxf((float)(end - beg), 1.0f);
    float v = fmaf(acc, inv, b[lane] + g_z[node * 32 + lane]);
    v = v > 0.f ? v : 0.01f * v;
    uint32_t jj = (uint32_t)(node * 32 + lane);
    g_h1[jj] = drop_bit<DK0.a, DK0.b>(jj) ? 0.f : 2.0f * v;
}

// layer 2 fused: gather-mean, GEMMs (4 nodes/warp, packed weights),
// dropout, l2norm
__global__ void __launch_bounds__(256) k_agg2(const float* __restrict__ Wl,
                       const float* __restrict__ b,
                       const float* __restrict__ Wr,
                       float* __restrict__ out) {
    __shared__ float2 swl2[32 * 32], swr2[32 * 32];   // 8KB + 8KB
    __shared__ float  rows[8][4][64];                 // 8KB
    int tid = threadIdx.x;
    for (int i = tid; i < 1024; i += 256) {
        int k = i >> 5, c = i & 31;
        swl2[i] = make_float2(Wl[k * 64 + c], Wl[k * 64 + 32 + c]);
        swr2[i] = make_float2(Wr[k * 64 + c], Wr[k * 64 + 32 + c]);
    }
    __syncthreads();
    int w = tid >> 5, lane = tid & 31;
    int nb = blockIdx.x * 32 + w * 4;                 // grid = 3125 exact
#pragma unroll
    for (int n = 0; n < 4; n++) {
        int node = nb + n;
        int beg = g_off[node], end = g_off[node + 1];
        float acc = gather_row<g_h1>(beg, end, lane);
        float inv = 1.0f / fmaxf((float)(end - beg), 1.0f);
        rows[w][n][lane]      = acc * inv;
        rows[w][n][32 + lane] = g_h1[node * 32 + lane];
    }
    __syncwarp();
    float bb0 = b[lane], bb1 = b[32 + lane];
    float a0[4], a1[4];
#pragma unroll
    for (int n = 0; n < 4; n++) { a0[n] = bb0; a1[n] = bb1; }
#pragma unroll
    for (int k = 0; k < 32; k++) {
        float2 wl = swl2[k * 32 + lane];
        float2 wr = swr2[k * 32 + lane];
#pragma unroll
        for (int n = 0; n < 4; n++) {
            float m = rows[w][n][k];
            float h = rows[w][n][32 + k];
            a0[n] = fmaf(m, wl.x, fmaf(h, wr.x, a0[n]));
            a1[n] = fmaf(m, wl.y, fmaf(h, wr.y, a1[n]));
        }
    }
#pragma unroll
    for (int n = 0; n < 4; n++) {
        int node = nb + n;
        uint32_t j0 = (uint32_t)(node * 64 + lane);
        float v0 = drop_bit<DK1.a, DK1.b>(j0)       ? 0.f : 2.0f * a0[n];
        float v1 = drop_bit<DK1.a, DK1.b>(j0 + 32u) ? 0.f : 2.0f * a1[n];
        float ss = v0 * v0 + v1 * v1;
#pragma unroll
        for (int o = 16; o > 0; o >>= 1)
            ss += __shfl_xor_sync(0xffffffffu, ss, o);
        float scale = 1.0f / fmaxf(sqrtf(ss), 1e-12f);
        out[node * 64 + lane]      = v0 * scale;
        out[node * 64 + 32 + lane] = v1 * scale;
    }
}

// ---------------- launch -----------------------------------------------------
// Fork/join inside graph capture: the CSR chain (zero/prep/scan/apply/bucket)
// runs on a side stream concurrently with the dense pre-GEMM on the main
// stream. Stream/event creation is host-side only (runs during the capture
// call, never during replay) and allocates no device memory.
extern "C" void kernel_launch(void* const* d_in, const int* in_sizes, int n_in,
                              void* d_out, int out_size) {
    const float*    x   = (const float*)d_in[0];
    const uint32_t* ei  = (const uint32_t*)d_in[1];   // int32 or int64 (detected)
    const float*    W1l = (const float*)d_in[2];
    const float*    b1  = (const float*)d_in[3];
    const float*    W1r = (const float*)d_in[4];
    const float*    W2l = (const float*)d_in[5];
    const float*    b2  = (const float*)d_in[6];
    const float*    W2r = (const float*)d_in[7];
    float* out = (float*)d_out;

    cudaStream_t s2;
    cudaStreamCreateWithFlags(&s2, cudaStreamNonBlocking);
    cudaEvent_t evFork, evJoin;
    cudaEventCreateWithFlags(&evFork, cudaEventDisableTiming);
    cudaEventCreateWithFlags(&evJoin, cudaEventDisableTiming);

    cudaEventRecord(evFork, 0);
    cudaStreamWaitEvent(s2, evFork, 0);

    // side stream: CSR build
    k_zero<<<(N_NODES / 256) + 1, 256, 0, s2>>>(ei);
    k_prep<<<(N_EDGES + 255) / 256, 256, 0, s2>>>(ei);
    k_scan_a<<<NSCAN_BLKS, SCAN_BLK, 0, s2>>>();
    k_apply<<<NSCAN_BLKS, SCAN_BLK, 0, s2>>>();
    k_bucket<<<(N_EDGES + 255) / 256, 256, 0, s2>>>();
    cudaEventRecord(evJoin, s2);

    // main stream: dense pre-GEMM (independent of CSR chain)
    k_pre<<<N_NODES / 32, 256>>>(x, W1l, W1r);

    cudaStreamWaitEvent(0, evJoin, 0);
    k_agg1<<<N_NODES / 8, 256>>>(b1);                  // 12500 blocks
    k_agg2<<<N_NODES / 32, 256>>>(W2l, b2, W2r, out);  // 3125 blocks

    cudaEventDestroy(evFork);
    cudaEventDestroy(evJoin);
    cudaStreamDestroy(s2);
}